// round 5
// baseline (speedup 1.0000x reference)
#include <cuda_runtime.h>
#include <cuda_fp16.h>
#include <math.h>

#define T_LEN   2048
#define TMASK   2047
#define NKEEP   1536
#define EDGE    256
#define NBC     16
#define NBAND   80
#define PHA_NB  50
#define AMP_NB  30
#define NBINS   18
#define NKTOT   640     // k = 1..634 used; sweep 0..639
#define NEV     160
#define KCH     80      // k per prefix chunk
#define NCH     8
#define AMP_STR 32      // padded amp row (halves)

// ---------------- f32x2 packed helpers (sm_103a) -----------------------------
typedef unsigned long long u64;
__device__ __forceinline__ u64 pk2(float lo, float hi) {
    u64 d; asm("mov.b64 %0,{%1,%2};" : "=l"(d) : "f"(lo), "f"(hi)); return d;
}
__device__ __forceinline__ void up2(u64 v, float& lo, float& hi) {
    asm("mov.b64 {%0,%1},%2;" : "=f"(lo), "=f"(hi) : "l"(v));
}
__device__ __forceinline__ u64 fma2(u64 a, u64 b, u64 c) {
    u64 d; asm("fma.rn.f32x2 %0,%1,%2,%3;" : "=l"(d) : "l"(a), "l"(b), "l"(c)); return d;
}
__device__ __forceinline__ u64 add2(u64 a, u64 b) {
    u64 d; asm("add.rn.f32x2 %0,%1,%2;" : "=l"(d) : "l"(a), "l"(b)); return d;
}
__device__ __forceinline__ u64 mul2(u64 a, u64 b) {
    u64 d; asm("mul.rn.f32x2 %0,%1,%2;" : "=l"(d) : "l"(a), "l"(b)); return d;
}

// ---------------- compile-time tables ---------------------------------------
struct Tables {
    int evk[NEV];
    int evslot[NEV];        // slot = 2*band + type(0=klo-1,1=khi)
    int evstart[NCH + 1];
    int cha[NBAND];         // chunk of klo-1
    int chb[NBAND];         // chunk of khi
};

constexpr Tables make_tables() {
    Tables tb{};
    int klo[NBAND] = {}, khi[NBAND] = {};
    for (int b = 0; b < NBAND; b++) {
        double lo_d = 0.0, hi_d = 0.0;
        if (b < PHA_NB) {
            double step = 18.0 / 49.0;
            double mid  = (b == PHA_NB - 1) ? 20.0 : ((double)b * step + 2.0);
            lo_d = mid * 0.75; hi_d = mid * 1.25;
        } else {
            int i = b - PHA_NB;
            double step = (141.0 - 60.0) / 29.0;
            double mid  = (i == AMP_NB - 1) ? 141.0 : ((double)i * step + 60.0);
            lo_d = mid * 0.875; hi_d = mid * 1.125;
        }
        float lo = (float)lo_d, hi = (float)hi_d;
        int kl = -1, kh = -2;
        for (int k = 1; k < NKTOT; k++) {
            float f = (float)k * 0.25f;
            if (f >= lo && f <= hi) { if (kl < 0) kl = k; kh = k; }
        }
        klo[b] = kl; khi[b] = kh;
        tb.cha[b] = (kl - 1) / KCH;
        tb.chb[b] = kh / KCH;
    }
    int key[NEV] = {}, slot[NEV] = {};
    for (int e = 0; e < NEV; e++) {
        int b = e >> 1, type = e & 1;
        key[e]  = type ? khi[b] : (klo[b] - 1);
        slot[e] = e;
    }
    for (int i = 1; i < NEV; i++) {
        int k2 = key[i], s2 = slot[i], j = i - 1;
        while (j >= 0 && key[j] > k2) { key[j+1] = key[j]; slot[j+1] = slot[j]; j--; }
        key[j+1] = k2; slot[j+1] = s2;
    }
    for (int e = 0; e < NEV; e++) { tb.evk[e] = key[e]; tb.evslot[e] = slot[e]; }
    for (int c = 0; c <= NCH; c++) {
        int s = 0;
        while (s < NEV && key[s] < c * KCH) s++;
        tb.evstart[c] = s;
    }
    return tb;
}
__constant__ Tables c_tab = make_tables();

// ---------------- scratch -----------------------------------------------------
__device__ float2        g_Xf[NBC][NKTOT];
__device__ float2        g_pref[NBC][NEV][NKEEP];
__device__ float2        g_ctot[NCH - 1][NBC][NKEEP];
__device__ unsigned char g_pidx[NBC][PHA_NB][NKEEP];
__device__ __half        g_amp[NBC][NKEEP][AMP_STR];   // padded row

// ---------------- kernel 1: fused 2-stage DFT (t = 32a + b) -----------------
__global__ __launch_bounds__(1024) void dft_kernel(const float* __restrict__ x) {
    __shared__ float  s_x[T_LEN];
    __shared__ float  s_twr[T_LEN], s_twi[T_LEN];
    __shared__ float  s_Yr[32 * 65], s_Yi[32 * 65];
    __shared__ float2 s_tw64[64];
    int bc = blockIdx.x, tid = threadIdx.x;
    for (int j = tid; j < T_LEN; j += 1024) {
        float s, c;
        sincospif((float)j * (1.0f / 1024.0f), &s, &c);
        s_twr[j] = c; s_twi[j] = s;
        s_x[j] = x[bc * T_LEN + j];
    }
    if (tid < 64) {
        float s, c;
        sincospif((float)tid * (1.0f / 32.0f), &s, &c);
        s_tw64[tid] = make_float2(c, -s);
    }
    __syncthreads();

    int b  = tid & 31;
    int mg = tid >> 5;
#pragma unroll
    for (int half = 0; half < 2; half++) {
        int m = mg + 32 * half;
        float ar = 0.f, ai = 0.f;
#pragma unroll 8
        for (int a = 0; a < 64; a++) {
            float  xv = s_x[(a << 5) + b];
            float2 w  = s_tw64[(m * a) & 63];
            ar = fmaf(xv, w.x, ar);
            ai = fmaf(xv, w.y, ai);
        }
        s_Yr[b * 65 + m] = ar;
        s_Yi[b * 65 + m] = ai;
    }
    __syncthreads();

    int k = tid;
    if (k < NKTOT) {
        int km = k & 63;
        float ar = 0.f, ai = 0.f;
#pragma unroll 8
        for (int b2 = 0; b2 < 32; b2++) {
            float yr = s_Yr[b2 * 65 + km];
            float yi = s_Yi[b2 * 65 + km];
            int id = (k * b2) & TMASK;
            float wr = s_twr[id], wi = s_twi[id];
            ar += yr * wr + yi * wi;
            ai += yi * wr - yr * wi;
        }
        g_Xf[bc][k] = make_float2(ar, ai);
    }
}

// ---------------- kernel 2: chunked prefix sweep, f32x2 packed --------------
// grid (12, 16, 8), block 128. No resync: rotator drift over 80 steps ~5e-7.
__global__ __launch_bounds__(128) void prefix_kernel() {
    __shared__ float2 s_XF[KCH];     // (Xr, Xi)
    __shared__ float2 s_XG[KCH];     // (-Xi, Xr)
    int bc  = blockIdx.y;
    int ch  = blockIdx.z;
    int k0  = ch * KCH;
    int tid = threadIdx.x;
    for (int j = tid; j < KCH; j += 128) {
        float2 X = g_Xf[bc][k0 + j];
        s_XF[j] = X;
        s_XG[j] = make_float2(-X.y, X.x);
    }
    __syncthreads();

    int tk = blockIdx.x * 128 + tid;
    int t  = EDGE + tk;
    float wr_, wi_;
    sincospif((float)t * (1.0f / 1024.0f), &wi_, &wr_);
    u64 Wr  = pk2(wr_, wr_);
    u64 Wi  = pk2(wi_, wi_);
    u64 WiN = pk2(-wi_, -wi_);
    float zr_, zi_;
    {
        int m = (k0 * t) & TMASK;
        sincospif((float)m * (1.0f / 1024.0f), &zi_, &zr_);
    }
    u64 Zr = pk2(zr_, zr_);
    u64 Zi = pk2(zi_, zi_);
    u64 Sa = 0ull, Sb = 0ull;

    int j    = c_tab.evstart[ch];
    int jend = c_tab.evstart[ch + 1];
    int nev  = (j < jend) ? c_tab.evk[j] : (1 << 30);

#pragma unroll
    for (int g = 0; g < KCH / 16; g++) {
        u64 Ca = 0ull, Cb = 0ull;
#pragma unroll
        for (int kk = 0; kk < 16; kk++) {
            int ks = g * 16 + kk;
            int k  = k0 + ks;
            u64 XF = *(const u64*)&s_XF[ks];
            u64 XG = *(const u64*)&s_XG[ks];
            Ca = fma2(Zr, XF, Ca);
            Cb = fma2(Zi, XG, Cb);
            if (k == nev) {
                do {
                    u64 tot = add2(add2(Sa, Ca), add2(Sb, Cb));
                    float vr, vi; up2(tot, vr, vi);
                    g_pref[bc][c_tab.evslot[j]][tk] = make_float2(vr, vi);
                    j++;
                    nev = (j < jend) ? c_tab.evk[j] : (1 << 30);
                } while (k == nev);
            }
            u64 nZr = fma2(Zi, WiN, mul2(Zr, Wr));
            u64 nZi = fma2(Zi, Wr,  mul2(Zr, Wi));
            Zr = nZr; Zi = nZi;
        }
        Sa = add2(Sa, Ca);
        Sb = add2(Sb, Cb);
    }
    if (ch < NCH - 1) {
        u64 tot = add2(Sa, Sb);
        float vr, vi; up2(tot, vr, vi);
        g_ctot[ch][bc][tk] = make_float2(vr, vi);
    }
}

// ---------------- kernel 3: band tail -- snapshots + chunk-prefix -----------
// grid (12, 16, 5), block 128; band group z covers 16 bands.
__global__ __launch_bounds__(128) void tail_kernel() {
    __shared__ float s_cumr[NCH][129], s_cumi[NCH][129];
    __shared__ float s_stage[128][17];
    int bc  = blockIdx.y;
    int bg  = blockIdx.z;
    int tid = threadIdx.x;
    int tk  = blockIdx.x * 128 + tid;

    float cr = 0.f, ci = 0.f;
    s_cumr[0][tid] = 0.f; s_cumi[0][tid] = 0.f;
#pragma unroll
    for (int ch = 1; ch < NCH; ch++) {
        float2 T = g_ctot[ch - 1][bc][tk];
        cr += T.x; ci += T.y;
        s_cumr[ch][tid] = cr; s_cumi[ch][tid] = ci;
    }
    __syncthreads();

    const float PIF    = 3.14159274101257324f;
    const float WIDTHF = (float)(2.0 * M_PI / (double)NBINS);
    int abase = (bg == 3) ? 0 : 14;
#pragma unroll
    for (int bb = 0; bb < 16; bb++) {
        int b = bg * 16 + bb;
        float2 pa = g_pref[bc][2 * b][tk];
        float2 pb = g_pref[bc][2 * b + 1][tk];
        int ca = c_tab.cha[b], cb = c_tab.chb[b];
        float re = (pb.x + s_cumr[cb][tid]) - (pa.x + s_cumr[ca][tid]);
        float im = (pb.y + s_cumi[cb][tid]) - (pa.y + s_cumi[ca][tid]);
        if (b < PHA_NB) {
            float ang = atan2f(im, re);
            float q   = __fdiv_rn(ang + PIF, WIDTHF);
            int   idx = (int)floorf(q);
            idx = max(0, min(idx, NBINS - 1));
            g_pidx[bc][b][tk] = (unsigned char)idx;
        } else {
            s_stage[tid][b - PHA_NB - abase] = sqrtf(re * re + im * im);
        }
    }
    __syncthreads();

    if (bg >= 3) {
        int ncol = (bg == 3) ? 14 : 16;
        unsigned int* dst = (unsigned int*)&g_amp[bc][tk][abase];
#pragma unroll
        for (int c = 0; c < 8; c++) {
            if (c < ncol / 2) {
                __half2 h2 = __floats2half2_rn(s_stage[tid][2 * c],
                                               s_stage[tid][2 * c + 1]);
                dst[c] = *(unsigned int*)&h2;
            }
        }
    }
}

// ---------------- kernel 4: binned sums + MI, one p per block ----------------
// grid (50, 16), block 256 (8 warps, 192 t each). Lanes 0..14 carry channel
// pairs (half2), lane 15 carries the count. Single RL chain per warp.
__global__ __launch_bounds__(256) void mi_kernel(float* __restrict__ out) {
    __shared__ unsigned int s_idx[NKEEP / 4];
    __shared__ float2 s_acc[8][NBINS][16];                // 18.4 KB
    int bc   = blockIdx.y;
    int p    = blockIdx.x;
    int tid  = threadIdx.x;
    int w    = tid >> 5;
    int lane = tid & 31;

    const unsigned int* src = (const unsigned int*)&g_pidx[bc][p][0];
    for (int j2 = tid; j2 < NKEEP / 4; j2 += 256) s_idx[j2] = src[j2];
    for (int j2 = tid; j2 < 8 * NBINS * 32; j2 += 256)
        ((float*)s_acc)[j2] = 0.f;
    __syncthreads();

    const __half2* amp2 = (const __half2*)&g_amp[bc][0][0];  // row = 16 half2
    int t0 = w * (NKEEP / 8);            // 192 t per warp
    bool isch  = lane < 15;
    float2 vcnt = (lane == 15) ? make_float2(1.f, 0.f) : make_float2(0.f, 0.f);

    int   kprev = -1;
    float2 run = make_float2(0.f, 0.f);
    for (int c = 0; c < (NKEEP / 8) / 4; c++) {
        int tl = t0 + c * 4;
        float2 v[4];
#pragma unroll
        for (int i = 0; i < 4; i++) {
            if (isch) v[i] = __half22float2(amp2[(tl + i) * 16 + lane]);
            else      v[i] = vcnt;
        }
        unsigned int word = s_idx[tl >> 2];
#pragma unroll
        for (int i = 0; i < 4; i++) {
            int b = (word >> (8 * i)) & 255;
            if (b != kprev) {                             // warp-uniform
                if (kprev >= 0 && lane < 16) {
                    float2 a = s_acc[w][kprev][lane];
                    a.x += run.x; a.y += run.y;
                    s_acc[w][kprev][lane] = a;
                }
                kprev = b; run = v[i];
            } else {
                run.x += v[i].x; run.y += v[i].y;
            }
        }
    }
    if (kprev >= 0 && lane < 16) {
        float2 a = s_acc[w][kprev][lane];
        a.x += run.x; a.y += run.y;
        s_acc[w][kprev][lane] = a;
    }
    __syncthreads();

    // final MI on warp 0; flat channel view: [0..29]=amp, [30]=count
    if (tid < 32) {
        float means[NBINS];
        float tot = 0.f;
#pragma unroll
        for (int k = 0; k < NBINS; k++) {
            float s = 0.f;
#pragma unroll
            for (int w8 = 0; w8 < 8; w8++)
                s += ((const float*)&s_acc[w8][k][0])[tid];
            float cnt = __shfl_sync(0xffffffffu, s, AMP_NB);
            float m   = __fdiv_rn(s, fmaxf(cnt, 1e-9f));
            means[k]  = m;
            tot      += m;
        }
        float denom = fmaxf(tot, 1e-9f);
        float acc = 0.f;
#pragma unroll
        for (int k = 0; k < NBINS; k++) {
            float pr = __fdiv_rn(means[k], denom);
            acc += pr * logf(pr + 1e-9f);
        }
        const float LOG_NB = 2.8903717578961645f;
        if (tid < AMP_NB)
            out[(bc * PHA_NB + p) * AMP_NB + tid] = (LOG_NB + acc) / LOG_NB;
    }
}

// ---------------- launch -----------------------------------------------------
extern "C" void kernel_launch(void* const* d_in, const int* in_sizes, int n_in,
                              void* d_out, int out_size) {
    const float* x = (const float*)d_in[0];
    float* out = (float*)d_out;

    dft_kernel<<<NBC, 1024>>>(x);
    prefix_kernel<<<dim3(NKEEP / 128, NBC, NCH), 128>>>();
    tail_kernel<<<dim3(NKEEP / 128, NBC, 5), 128>>>();
    mi_kernel<<<dim3(PHA_NB, NBC), 256>>>(out);
}

// round 6
// speedup vs baseline: 1.0004x; 1.0004x over previous
#include <cuda_runtime.h>
#include <cuda_fp16.h>
#include <math.h>

#define T_LEN   2048
#define TMASK   2047
#define NKEEP   1536
#define EDGE    256
#define NBC     16
#define NBAND   80
#define PHA_NB  50
#define AMP_NB  30
#define NBINS   18
#define NKTOT   640
#define NEV     160
#define KCH     80
#define NCH     8
#define AMP_STR 32          // padded amp row (halves); col30=count, col31=0
#define TS2     2
#define TPB2    (NKEEP / TS2)   // 768 t per mi block

// ---------------- f32x2 packed helpers (sm_103a) -----------------------------
typedef unsigned long long u64;
__device__ __forceinline__ u64 pk2(float lo, float hi) {
    u64 d; asm("mov.b64 %0,{%1,%2};" : "=l"(d) : "f"(lo), "f"(hi)); return d;
}
__device__ __forceinline__ void up2(u64 v, float& lo, float& hi) {
    asm("mov.b64 {%0,%1},%2;" : "=f"(lo), "=f"(hi) : "l"(v));
}
__device__ __forceinline__ u64 fma2(u64 a, u64 b, u64 c) {
    u64 d; asm("fma.rn.f32x2 %0,%1,%2,%3;" : "=l"(d) : "l"(a), "l"(b), "l"(c)); return d;
}
__device__ __forceinline__ u64 add2(u64 a, u64 b) {
    u64 d; asm("add.rn.f32x2 %0,%1,%2;" : "=l"(d) : "l"(a), "l"(b)); return d;
}
__device__ __forceinline__ u64 mul2(u64 a, u64 b) {
    u64 d; asm("mul.rn.f32x2 %0,%1,%2;" : "=l"(d) : "l"(a), "l"(b)); return d;
}

// ---------------- compile-time tables ---------------------------------------
struct Tables {
    int evk[NEV];
    int evslot[NEV];
    int evstart[NCH + 1];
    int cha[NBAND];
    int chb[NBAND];
};

constexpr Tables make_tables() {
    Tables tb{};
    int klo[NBAND] = {}, khi[NBAND] = {};
    for (int b = 0; b < NBAND; b++) {
        double lo_d = 0.0, hi_d = 0.0;
        if (b < PHA_NB) {
            double step = 18.0 / 49.0;
            double mid  = (b == PHA_NB - 1) ? 20.0 : ((double)b * step + 2.0);
            lo_d = mid * 0.75; hi_d = mid * 1.25;
        } else {
            int i = b - PHA_NB;
            double step = (141.0 - 60.0) / 29.0;
            double mid  = (i == AMP_NB - 1) ? 141.0 : ((double)i * step + 60.0);
            lo_d = mid * 0.875; hi_d = mid * 1.125;
        }
        float lo = (float)lo_d, hi = (float)hi_d;
        int kl = -1, kh = -2;
        for (int k = 1; k < NKTOT; k++) {
            float f = (float)k * 0.25f;
            if (f >= lo && f <= hi) { if (kl < 0) kl = k; kh = k; }
        }
        klo[b] = kl; khi[b] = kh;
        tb.cha[b] = (kl - 1) / KCH;
        tb.chb[b] = kh / KCH;
    }
    int key[NEV] = {}, slot[NEV] = {};
    for (int e = 0; e < NEV; e++) {
        int b = e >> 1, type = e & 1;
        key[e]  = type ? khi[b] : (klo[b] - 1);
        slot[e] = e;
    }
    for (int i = 1; i < NEV; i++) {
        int k2 = key[i], s2 = slot[i], j = i - 1;
        while (j >= 0 && key[j] > k2) { key[j+1] = key[j]; slot[j+1] = slot[j]; j--; }
        key[j+1] = k2; slot[j+1] = s2;
    }
    for (int e = 0; e < NEV; e++) { tb.evk[e] = key[e]; tb.evslot[e] = slot[e]; }
    for (int c = 0; c <= NCH; c++) {
        int s = 0;
        while (s < NEV && key[s] < c * KCH) s++;
        tb.evstart[c] = s;
    }
    return tb;
}
__constant__ Tables c_tab = make_tables();

// ---------------- scratch -----------------------------------------------------
__device__ float2        g_Xf[NBC][NKTOT];
__device__ float2        g_pref[NBC][NEV][NKEEP];
__device__ float2        g_ctot[NCH - 1][NBC][NKEEP];
__device__ unsigned char g_pidx[NBC][PHA_NB][NKEEP];
__device__ __half        g_amp[NBC][NKEEP][AMP_STR];
__device__ float2        g_part[NBC][PHA_NB][TS2][NBINS][16];

// ---------------- kernel 1: fused 2-stage DFT (t = 32a + b) -----------------
__global__ __launch_bounds__(1024) void dft_kernel(const float* __restrict__ x) {
    __shared__ float  s_x[T_LEN];
    __shared__ float  s_twr[T_LEN], s_twi[T_LEN];
    __shared__ float  s_Yr[32 * 65], s_Yi[32 * 65];
    __shared__ float2 s_tw64[64];
    int bc = blockIdx.x, tid = threadIdx.x;
    for (int j = tid; j < T_LEN; j += 1024) {
        float s, c;
        sincospif((float)j * (1.0f / 1024.0f), &s, &c);
        s_twr[j] = c; s_twi[j] = s;
        s_x[j] = x[bc * T_LEN + j];
    }
    if (tid < 64) {
        float s, c;
        sincospif((float)tid * (1.0f / 32.0f), &s, &c);
        s_tw64[tid] = make_float2(c, -s);
    }
    __syncthreads();

    int b  = tid & 31;
    int mg = tid >> 5;
#pragma unroll
    for (int half = 0; half < 2; half++) {
        int m = mg + 32 * half;
        float ar = 0.f, ai = 0.f;
#pragma unroll 8
        for (int a = 0; a < 64; a++) {
            float  xv = s_x[(a << 5) + b];
            float2 w  = s_tw64[(m * a) & 63];
            ar = fmaf(xv, w.x, ar);
            ai = fmaf(xv, w.y, ai);
        }
        s_Yr[b * 65 + m] = ar;
        s_Yi[b * 65 + m] = ai;
    }
    __syncthreads();

    int k = tid;
    if (k < NKTOT) {
        int km = k & 63;
        float ar = 0.f, ai = 0.f;
#pragma unroll 8
        for (int b2 = 0; b2 < 32; b2++) {
            float yr = s_Yr[b2 * 65 + km];
            float yi = s_Yi[b2 * 65 + km];
            int id = (k * b2) & TMASK;
            float wr = s_twr[id], wi = s_twi[id];
            ar += yr * wr + yi * wi;
            ai += yi * wr - yr * wi;
        }
        g_Xf[bc][k] = make_float2(ar, ai);
    }
}

// ---------------- kernel 2: chunked prefix sweep, f32x2 packed --------------
__global__ __launch_bounds__(128) void prefix_kernel() {
    __shared__ float2 s_XF[KCH];
    __shared__ float2 s_XG[KCH];
    int bc  = blockIdx.y;
    int ch  = blockIdx.z;
    int k0  = ch * KCH;
    int tid = threadIdx.x;
    for (int j = tid; j < KCH; j += 128) {
        float2 X = g_Xf[bc][k0 + j];
        s_XF[j] = X;
        s_XG[j] = make_float2(-X.y, X.x);
    }
    __syncthreads();

    int tk = blockIdx.x * 128 + tid;
    int t  = EDGE + tk;
    float wr_, wi_;
    sincospif((float)t * (1.0f / 1024.0f), &wi_, &wr_);
    u64 Wr  = pk2(wr_, wr_);
    u64 Wi  = pk2(wi_, wi_);
    u64 WiN = pk2(-wi_, -wi_);
    float zr_, zi_;
    {
        int m = (k0 * t) & TMASK;
        sincospif((float)m * (1.0f / 1024.0f), &zi_, &zr_);
    }
    u64 Zr = pk2(zr_, zr_);
    u64 Zi = pk2(zi_, zi_);
    u64 Sa = 0ull, Sb = 0ull;

    int j    = c_tab.evstart[ch];
    int jend = c_tab.evstart[ch + 1];
    int nev  = (j < jend) ? c_tab.evk[j] : (1 << 30);

#pragma unroll
    for (int g = 0; g < KCH / 16; g++) {
        u64 Ca = 0ull, Cb = 0ull;
#pragma unroll
        for (int kk = 0; kk < 16; kk++) {
            int ks = g * 16 + kk;
            int k  = k0 + ks;
            u64 XF = *(const u64*)&s_XF[ks];
            u64 XG = *(const u64*)&s_XG[ks];
            Ca = fma2(Zr, XF, Ca);
            Cb = fma2(Zi, XG, Cb);
            if (k == nev) {
                do {
                    u64 tot = add2(add2(Sa, Ca), add2(Sb, Cb));
                    float vr, vi; up2(tot, vr, vi);
                    g_pref[bc][c_tab.evslot[j]][tk] = make_float2(vr, vi);
                    j++;
                    nev = (j < jend) ? c_tab.evk[j] : (1 << 30);
                } while (k == nev);
            }
            u64 nZr = fma2(Zi, WiN, mul2(Zr, Wr));
            u64 nZi = fma2(Zi, Wr,  mul2(Zr, Wi));
            Zr = nZr; Zi = nZi;
        }
        Sa = add2(Sa, Ca);
        Sb = add2(Sb, Cb);
    }
    if (ch < NCH - 1) {
        u64 tot = add2(Sa, Sb);
        float vr, vi; up2(tot, vr, vi);
        g_ctot[ch][bc][tk] = make_float2(vr, vi);
    }
}

// ---------------- kernel 3: band tail -- snapshots + chunk-prefix -----------
__global__ __launch_bounds__(128) void tail_kernel() {
    __shared__ float s_cumr[NCH][129], s_cumi[NCH][129];
    __shared__ float s_stage[128][17];
    int bc  = blockIdx.y;
    int bg  = blockIdx.z;
    int tid = threadIdx.x;
    int tk  = blockIdx.x * 128 + tid;

    float cr = 0.f, ci = 0.f;
    s_cumr[0][tid] = 0.f; s_cumi[0][tid] = 0.f;
#pragma unroll
    for (int ch = 1; ch < NCH; ch++) {
        float2 T = g_ctot[ch - 1][bc][tk];
        cr += T.x; ci += T.y;
        s_cumr[ch][tid] = cr; s_cumi[ch][tid] = ci;
    }
    __syncthreads();

    const float PIF    = 3.14159274101257324f;
    const float WIDTHF = (float)(2.0 * M_PI / (double)NBINS);
    int abase = (bg == 3) ? 0 : 14;
#pragma unroll
    for (int bb = 0; bb < 16; bb++) {
        int b = bg * 16 + bb;
        float2 pa = g_pref[bc][2 * b][tk];
        float2 pb = g_pref[bc][2 * b + 1][tk];
        int ca = c_tab.cha[b], cb = c_tab.chb[b];
        float re = (pb.x + s_cumr[cb][tid]) - (pa.x + s_cumr[ca][tid]);
        float im = (pb.y + s_cumi[cb][tid]) - (pa.y + s_cumi[ca][tid]);
        if (b < PHA_NB) {
            float ang = atan2f(im, re);
            float q   = __fdiv_rn(ang + PIF, WIDTHF);
            int   idx = (int)floorf(q);
            idx = max(0, min(idx, NBINS - 1));
            g_pidx[bc][b][tk] = (unsigned char)idx;
        } else {
            s_stage[tid][b - PHA_NB - abase] = sqrtf(re * re + im * im);
        }
    }
    __syncthreads();

    if (bg >= 3) {
        int ncol = (bg == 3) ? 14 : 16;
        unsigned int* dst = (unsigned int*)&g_amp[bc][tk][abase];
#pragma unroll
        for (int c = 0; c < 8; c++) {
            if (c < ncol / 2) {
                __half2 h2 = __floats2half2_rn(s_stage[tid][2 * c],
                                               s_stage[tid][2 * c + 1]);
                dst[c] = *(unsigned int*)&h2;
            }
        }
        if (bg == 4) {                    // count channel: col30=1, col31=0
            __half2 one = __floats2half2_rn(1.0f, 0.0f);
            dst[8] = *(unsigned int*)&one;
        }
    }
}

// ---------------- kernel 4: partial binned sums ------------------------------
// grid (25, 16, 2), block 128 (4 warps). lane = stream(2) x channel-pair(16);
// every lane productive; 2 p's share each amp load; per-lane predicated RL.
__global__ __launch_bounds__(128) void mi_part_kernel() {
    __shared__ unsigned char s_idx[2][TPB2];          // 1.5 KB
    __shared__ float2 s_acc[4][2][NBINS][32];         // 36.9 KB
    int bc  = blockIdx.y;
    int p0  = blockIdx.x * 2;
    int z   = blockIdx.z;
    int tid = threadIdx.x;
    int w   = tid >> 5;
    int lane = tid & 31;
    int c   = lane & 15;

    for (int pp = 0; pp < 2; pp++) {
        const unsigned int* src =
            (const unsigned int*)&g_pidx[bc][p0 + pp][z * TPB2];
        unsigned int* dst = (unsigned int*)&s_idx[pp][0];
        for (int j = tid; j < TPB2 / 4; j += 128) dst[j] = src[j];
    }
    {
        float4* a4 = (float4*)s_acc;
        for (int j = tid; j < 4 * 2 * NBINS * 32 / 2; j += 128)
            a4[j] = make_float4(0.f, 0.f, 0.f, 0.f);
    }
    __syncthreads();

    const __half2* amp2 = (const __half2*)&g_amp[bc][z * TPB2][0];
    int tb = w * 192 + (lane >> 4) * 96;              // local t base, 96 steps

    int kp0 = -1, kp1 = -1;
    float2 run0 = make_float2(0.f, 0.f);
    float2 run1 = make_float2(0.f, 0.f);
    for (int i0 = 0; i0 < 96; i0 += 4) {
        float2 v[4];
#pragma unroll
        for (int i = 0; i < 4; i++)
            v[i] = __half22float2(amp2[(tb + i0 + i) * 16 + c]);
#pragma unroll
        for (int i = 0; i < 4; i++) {
            int t  = tb + i0 + i;
            int b0 = s_idx[0][t];
            int b1 = s_idx[1][t];
            if (b0 != kp0) {                          // half-warp-uniform
                if (kp0 >= 0) {
                    float2 a = s_acc[w][0][kp0][lane];
                    a.x += run0.x; a.y += run0.y;
                    s_acc[w][0][kp0][lane] = a;
                }
                kp0 = b0; run0 = v[i];
            } else { run0.x += v[i].x; run0.y += v[i].y; }
            if (b1 != kp1) {
                if (kp1 >= 0) {
                    float2 a = s_acc[w][1][kp1][lane];
                    a.x += run1.x; a.y += run1.y;
                    s_acc[w][1][kp1][lane] = a;
                }
                kp1 = b1; run1 = v[i];
            } else { run1.x += v[i].x; run1.y += v[i].y; }
        }
    }
    {
        float2 a = s_acc[w][0][kp0][lane];
        a.x += run0.x; a.y += run0.y;
        s_acc[w][0][kp0][lane] = a;
        float2 b = s_acc[w][1][kp1][lane];
        b.x += run1.x; b.y += run1.y;
        s_acc[w][1][kp1][lane] = b;
    }
    __syncthreads();

    // merge warps + stream halves -> g_part[bc][p][z][k][16]
    for (int j = tid; j < 2 * NBINS * 16; j += 128) {
        int pp = j / (NBINS * 16);
        int r  = j % (NBINS * 16);
        int k  = r >> 4;
        int ch = r & 15;
        float2 acc = make_float2(0.f, 0.f);
#pragma unroll
        for (int w4 = 0; w4 < 4; w4++) {
            float2 a = s_acc[w4][pp][k][ch];
            float2 b = s_acc[w4][pp][k][ch + 16];
            acc.x += a.x + b.x;
            acc.y += a.y + b.y;
        }
        g_part[bc][p0 + pp][z][k][ch] = acc;
    }
}

// ---------------- kernel 5: reduce partials + MI ------------------------------
// grid (50, 16), block 32. lane c<15 covers channels (2c, 2c+1); lane15 = count.
__global__ __launch_bounds__(32) void mi_reduce_kernel(float* __restrict__ out) {
    int bc   = blockIdx.y;
    int p    = blockIdx.x;
    int lane = threadIdx.x;
    int cl   = lane & 15;

    float2 means[NBINS];
    float2 tot = make_float2(0.f, 0.f);
#pragma unroll
    for (int k = 0; k < NBINS; k++) {
        float2 a = g_part[bc][p][0][k][cl];
        float2 b = g_part[bc][p][1][k][cl];
        float2 s = make_float2(a.x + b.x, a.y + b.y);
        float cnt = __shfl_sync(0xffffffffu, s.x, 15);
        float inv = __fdiv_rn(1.0f, fmaxf(cnt, 1e-9f));
        float2 m  = make_float2(s.x * inv, s.y * inv);
        // NOTE: ref divides each sum by count; mul-by-recip differs in ulp.
        // use explicit divides to match ref rounding:
        m.x = __fdiv_rn(s.x, fmaxf(cnt, 1e-9f));
        m.y = __fdiv_rn(s.y, fmaxf(cnt, 1e-9f));
        means[k] = m;
        tot.x += m.x; tot.y += m.y;
    }
    float2 denom = make_float2(fmaxf(tot.x, 1e-9f), fmaxf(tot.y, 1e-9f));
    float2 acc = make_float2(0.f, 0.f);
#pragma unroll
    for (int k = 0; k < NBINS; k++) {
        float prx = __fdiv_rn(means[k].x, denom.x);
        float pry = __fdiv_rn(means[k].y, denom.y);
        acc.x += prx * logf(prx + 1e-9f);
        acc.y += pry * logf(pry + 1e-9f);
    }
    const float LOG_NB = 2.8903717578961645f;
    if (lane < 15) {
        float* o = &out[(bc * PHA_NB + p) * AMP_NB];
        o[2 * lane]     = (LOG_NB + acc.x) / LOG_NB;
        o[2 * lane + 1] = (LOG_NB + acc.y) / LOG_NB;
    }
}

// ---------------- launch -----------------------------------------------------
extern "C" void kernel_launch(void* const* d_in, const int* in_sizes, int n_in,
                              void* d_out, int out_size) {
    const float* x = (const float*)d_in[0];
    float* out = (float*)d_out;

    dft_kernel<<<NBC, 1024>>>(x);
    prefix_kernel<<<dim3(NKEEP / 128, NBC, NCH), 128>>>();
    tail_kernel<<<dim3(NKEEP / 128, NBC, 5), 128>>>();
    mi_part_kernel<<<dim3(PHA_NB / 2, NBC, TS2), 128>>>();
    mi_reduce_kernel<<<dim3(PHA_NB, NBC), 32>>>(out);
}

// round 7
// speedup vs baseline: 1.1701x; 1.1697x over previous
#include <cuda_runtime.h>
#include <cuda_fp16.h>
#include <math.h>

#define T_LEN   2048
#define TMASK   2047
#define NKEEP   1536
#define EDGE    256
#define NBC     16
#define NBAND   80
#define PHA_NB  50
#define AMP_NB  30
#define NBINS   18
#define NKTOT   640
#define NEV     160
#define KCH     80
#define NCH     8
#define AMP_STR 32          // padded amp row (halves); col30=count, col31=0
#define TS2     4
#define TPB2    (NKEEP / TS2)   // 384 t per mi block

// ---------------- f32x2 packed helpers (sm_103a) -----------------------------
typedef unsigned long long u64;
__device__ __forceinline__ u64 pk2(float lo, float hi) {
    u64 d; asm("mov.b64 %0,{%1,%2};" : "=l"(d) : "f"(lo), "f"(hi)); return d;
}
__device__ __forceinline__ void up2(u64 v, float& lo, float& hi) {
    asm("mov.b64 {%0,%1},%2;" : "=f"(lo), "=f"(hi) : "l"(v));
}
__device__ __forceinline__ u64 fma2(u64 a, u64 b, u64 c) {
    u64 d; asm("fma.rn.f32x2 %0,%1,%2,%3;" : "=l"(d) : "l"(a), "l"(b), "l"(c)); return d;
}
__device__ __forceinline__ u64 add2(u64 a, u64 b) {
    u64 d; asm("add.rn.f32x2 %0,%1,%2;" : "=l"(d) : "l"(a), "l"(b)); return d;
}
__device__ __forceinline__ u64 mul2(u64 a, u64 b) {
    u64 d; asm("mul.rn.f32x2 %0,%1,%2;" : "=l"(d) : "l"(a), "l"(b)); return d;
}

// ---------------- compile-time tables ---------------------------------------
struct Tables {
    int evk[NEV];
    int evslot[NEV];
    int evstart[NCH + 1];
    int cha[NBAND];
    int chb[NBAND];
};

constexpr Tables make_tables() {
    Tables tb{};
    int klo[NBAND] = {}, khi[NBAND] = {};
    for (int b = 0; b < NBAND; b++) {
        double lo_d = 0.0, hi_d = 0.0;
        if (b < PHA_NB) {
            double step = 18.0 / 49.0;
            double mid  = (b == PHA_NB - 1) ? 20.0 : ((double)b * step + 2.0);
            lo_d = mid * 0.75; hi_d = mid * 1.25;
        } else {
            int i = b - PHA_NB;
            double step = (141.0 - 60.0) / 29.0;
            double mid  = (i == AMP_NB - 1) ? 141.0 : ((double)i * step + 60.0);
            lo_d = mid * 0.875; hi_d = mid * 1.125;
        }
        float lo = (float)lo_d, hi = (float)hi_d;
        int kl = -1, kh = -2;
        for (int k = 1; k < NKTOT; k++) {
            float f = (float)k * 0.25f;
            if (f >= lo && f <= hi) { if (kl < 0) kl = k; kh = k; }
        }
        klo[b] = kl; khi[b] = kh;
        tb.cha[b] = (kl - 1) / KCH;
        tb.chb[b] = kh / KCH;
    }
    int key[NEV] = {}, slot[NEV] = {};
    for (int e = 0; e < NEV; e++) {
        int b = e >> 1, type = e & 1;
        key[e]  = type ? khi[b] : (klo[b] - 1);
        slot[e] = e;
    }
    for (int i = 1; i < NEV; i++) {
        int k2 = key[i], s2 = slot[i], j = i - 1;
        while (j >= 0 && key[j] > k2) { key[j+1] = key[j]; slot[j+1] = slot[j]; j--; }
        key[j+1] = k2; slot[j+1] = s2;
    }
    for (int e = 0; e < NEV; e++) { tb.evk[e] = key[e]; tb.evslot[e] = slot[e]; }
    for (int c = 0; c <= NCH; c++) {
        int s = 0;
        while (s < NEV && key[s] < c * KCH) s++;
        tb.evstart[c] = s;
    }
    return tb;
}
__constant__ Tables c_tab = make_tables();

// ---------------- scratch -----------------------------------------------------
__device__ float2        g_Xf[NBC][NKTOT];
__device__ float2        g_pref[NBC][NEV][NKEEP];
__device__ float2        g_ctot[NCH - 1][NBC][NKEEP];
__device__ unsigned char g_pidx[NBC][PHA_NB][NKEEP];
__device__ __half        g_amp[NBC][NKEEP][AMP_STR];
__device__ float2        g_part[NBC][PHA_NB][TS2][NBINS][16];
__device__ int           g_cnt[NBC][PHA_NB / 2];

// ---------------- kernel 1: fused 2-stage DFT (t = 32a + b) -----------------
__global__ __launch_bounds__(1024) void dft_kernel(const float* __restrict__ x) {
    __shared__ float  s_x[T_LEN];
    __shared__ float  s_twr[T_LEN], s_twi[T_LEN];
    __shared__ float  s_Yr[32 * 65], s_Yi[32 * 65];
    __shared__ float2 s_tw64[64];
    int bc = blockIdx.x, tid = threadIdx.x;
    if (tid < PHA_NB / 2) g_cnt[bc][tid] = 0;      // reset fusion counters
    for (int j = tid; j < T_LEN; j += 1024) {
        float s, c;
        sincospif((float)j * (1.0f / 1024.0f), &s, &c);
        s_twr[j] = c; s_twi[j] = s;
        s_x[j] = x[bc * T_LEN + j];
    }
    if (tid < 64) {
        float s, c;
        sincospif((float)tid * (1.0f / 32.0f), &s, &c);
        s_tw64[tid] = make_float2(c, -s);
    }
    __syncthreads();

    int b  = tid & 31;
    int mg = tid >> 5;
#pragma unroll
    for (int half = 0; half < 2; half++) {
        int m = mg + 32 * half;
        float ar = 0.f, ai = 0.f;
#pragma unroll 8
        for (int a = 0; a < 64; a++) {
            float  xv = s_x[(a << 5) + b];
            float2 w  = s_tw64[(m * a) & 63];
            ar = fmaf(xv, w.x, ar);
            ai = fmaf(xv, w.y, ai);
        }
        s_Yr[b * 65 + m] = ar;
        s_Yi[b * 65 + m] = ai;
    }
    __syncthreads();

    int k = tid;
    if (k < NKTOT) {
        int km = k & 63;
        float ar = 0.f, ai = 0.f;
#pragma unroll 8
        for (int b2 = 0; b2 < 32; b2++) {
            float yr = s_Yr[b2 * 65 + km];
            float yi = s_Yi[b2 * 65 + km];
            int id = (k * b2) & TMASK;
            float wr = s_twr[id], wi = s_twi[id];
            ar += yr * wr + yi * wi;
            ai += yi * wr - yr * wi;
        }
        g_Xf[bc][k] = make_float2(ar, ai);
    }
}

// ---------------- kernel 2: chunked prefix sweep, f32x2 packed --------------
__global__ __launch_bounds__(128) void prefix_kernel() {
    __shared__ float2 s_XF[KCH];
    __shared__ float2 s_XG[KCH];
    int bc  = blockIdx.y;
    int ch  = blockIdx.z;
    int k0  = ch * KCH;
    int tid = threadIdx.x;
    for (int j = tid; j < KCH; j += 128) {
        float2 X = g_Xf[bc][k0 + j];
        s_XF[j] = X;
        s_XG[j] = make_float2(-X.y, X.x);
    }
    __syncthreads();

    int tk = blockIdx.x * 128 + tid;
    int t  = EDGE + tk;
    float wr_, wi_;
    sincospif((float)t * (1.0f / 1024.0f), &wi_, &wr_);
    u64 Wr  = pk2(wr_, wr_);
    u64 Wi  = pk2(wi_, wi_);
    u64 WiN = pk2(-wi_, -wi_);
    float zr_, zi_;
    {
        int m = (k0 * t) & TMASK;
        sincospif((float)m * (1.0f / 1024.0f), &zi_, &zr_);
    }
    u64 Zr = pk2(zr_, zr_);
    u64 Zi = pk2(zi_, zi_);
    u64 Sa = 0ull, Sb = 0ull;

    int j    = c_tab.evstart[ch];
    int jend = c_tab.evstart[ch + 1];
    int nev  = (j < jend) ? c_tab.evk[j] : (1 << 30);

#pragma unroll
    for (int g = 0; g < KCH / 16; g++) {
        u64 Ca = 0ull, Cb = 0ull;
#pragma unroll
        for (int kk = 0; kk < 16; kk++) {
            int ks = g * 16 + kk;
            int k  = k0 + ks;
            u64 XF = *(const u64*)&s_XF[ks];
            u64 XG = *(const u64*)&s_XG[ks];
            Ca = fma2(Zr, XF, Ca);
            Cb = fma2(Zi, XG, Cb);
            if (k == nev) {
                do {
                    u64 tot = add2(add2(Sa, Ca), add2(Sb, Cb));
                    float vr, vi; up2(tot, vr, vi);
                    g_pref[bc][c_tab.evslot[j]][tk] = make_float2(vr, vi);
                    j++;
                    nev = (j < jend) ? c_tab.evk[j] : (1 << 30);
                } while (k == nev);
            }
            u64 nZr = fma2(Zi, WiN, mul2(Zr, Wr));
            u64 nZi = fma2(Zi, Wr,  mul2(Zr, Wi));
            Zr = nZr; Zi = nZi;
        }
        Sa = add2(Sa, Ca);
        Sb = add2(Sb, Cb);
    }
    if (ch < NCH - 1) {
        u64 tot = add2(Sa, Sb);
        float vr, vi; up2(tot, vr, vi);
        g_ctot[ch][bc][tk] = make_float2(vr, vi);
    }
}

// ---------------- kernel 3: band tail -- snapshots + chunk-prefix -----------
__global__ __launch_bounds__(128) void tail_kernel() {
    __shared__ float s_cumr[NCH][129], s_cumi[NCH][129];
    __shared__ float s_stage[128][17];
    int bc  = blockIdx.y;
    int bg  = blockIdx.z;
    int tid = threadIdx.x;
    int tk  = blockIdx.x * 128 + tid;

    float cr = 0.f, ci = 0.f;
    s_cumr[0][tid] = 0.f; s_cumi[0][tid] = 0.f;
#pragma unroll
    for (int ch = 1; ch < NCH; ch++) {
        float2 T = g_ctot[ch - 1][bc][tk];
        cr += T.x; ci += T.y;
        s_cumr[ch][tid] = cr; s_cumi[ch][tid] = ci;
    }
    __syncthreads();

    const float PIF    = 3.14159274101257324f;
    const float WIDTHF = (float)(2.0 * M_PI / (double)NBINS);
    int abase = (bg == 3) ? 0 : 14;
#pragma unroll
    for (int bb = 0; bb < 16; bb++) {
        int b = bg * 16 + bb;
        float2 pa = g_pref[bc][2 * b][tk];
        float2 pb = g_pref[bc][2 * b + 1][tk];
        int ca = c_tab.cha[b], cb = c_tab.chb[b];
        float re = (pb.x + s_cumr[cb][tid]) - (pa.x + s_cumr[ca][tid]);
        float im = (pb.y + s_cumi[cb][tid]) - (pa.y + s_cumi[ca][tid]);
        if (b < PHA_NB) {
            float ang = atan2f(im, re);
            float q   = __fdiv_rn(ang + PIF, WIDTHF);
            int   idx = (int)floorf(q);
            idx = max(0, min(idx, NBINS - 1));
            g_pidx[bc][b][tk] = (unsigned char)idx;
        } else {
            s_stage[tid][b - PHA_NB - abase] = sqrtf(re * re + im * im);
        }
    }
    __syncthreads();

    if (bg >= 3) {
        int ncol = (bg == 3) ? 14 : 16;
        unsigned int* dst = (unsigned int*)&g_amp[bc][tk][abase];
#pragma unroll
        for (int c = 0; c < 8; c++) {
            if (c < ncol / 2) {
                __half2 h2 = __floats2half2_rn(s_stage[tid][2 * c],
                                               s_stage[tid][2 * c + 1]);
                dst[c] = *(unsigned int*)&h2;
            }
        }
        if (bg == 4) {                    // count channel: col30=1, col31=0
            __half2 one = __floats2half2_rn(1.0f, 0.0f);
            dst[8] = *(unsigned int*)&one;
        }
    }
}

// ---------------- kernel 4: binned sums + fused MI reduce --------------------
// grid (25, 16, 4), block 64 (2 warps) -- entire grid resident in ONE wave.
// lane = stream(2) x channel-pair(16); 2 p's share each amp load; word-shift
// idx extraction; last block per (bc, p-pair) reduces partials and emits MI.
__global__ __launch_bounds__(64) void mi_part_kernel(float* __restrict__ out) {
    __shared__ unsigned int s_idxw[2][TPB2 / 4];      // 768 B
    __shared__ float2 s_acc[2][2][NBINS][32];         // 18.4 KB
    __shared__ int s_old;
    int bc  = blockIdx.y;
    int px  = blockIdx.x;
    int p0  = px * 2;
    int z   = blockIdx.z;
    int tid = threadIdx.x;
    int w   = tid >> 5;
    int lane = tid & 31;
    int c   = lane & 15;

    for (int pp = 0; pp < 2; pp++) {
        const unsigned int* src =
            (const unsigned int*)&g_pidx[bc][p0 + pp][z * TPB2];
        for (int j = tid; j < TPB2 / 4; j += 64) s_idxw[pp][j] = src[j];
    }
    {
        float4* a4 = (float4*)s_acc;
        for (int j = tid; j < 2 * 2 * NBINS * 32 / 2; j += 64)
            a4[j] = make_float4(0.f, 0.f, 0.f, 0.f);
    }
    __syncthreads();

    const __half2* amp2 = (const __half2*)&g_amp[bc][z * TPB2][0];
    int tb = w * 192 + (lane >> 4) * 96;              // local t base, 96 steps

    int kp0 = -1, kp1 = -1;
    float2 run0 = make_float2(0.f, 0.f);
    float2 run1 = make_float2(0.f, 0.f);
    for (int i0 = 0; i0 < 96; i0 += 4) {
        float2 v[4];
#pragma unroll
        for (int i = 0; i < 4; i++)
            v[i] = __half22float2(amp2[(tb + i0 + i) * 16 + c]);
        unsigned int w0 = s_idxw[0][(tb + i0) >> 2];
        unsigned int w1 = s_idxw[1][(tb + i0) >> 2];
#pragma unroll
        for (int i = 0; i < 4; i++) {
            int b0 = (w0 >> (8 * i)) & 255;
            int b1 = (w1 >> (8 * i)) & 255;
            if (b0 != kp0) {
                if (kp0 >= 0) {
                    float2 a = s_acc[w][0][kp0][lane];
                    a.x += run0.x; a.y += run0.y;
                    s_acc[w][0][kp0][lane] = a;
                }
                kp0 = b0; run0 = v[i];
            } else { run0.x += v[i].x; run0.y += v[i].y; }
            if (b1 != kp1) {
                if (kp1 >= 0) {
                    float2 a = s_acc[w][1][kp1][lane];
                    a.x += run1.x; a.y += run1.y;
                    s_acc[w][1][kp1][lane] = a;
                }
                kp1 = b1; run1 = v[i];
            } else { run1.x += v[i].x; run1.y += v[i].y; }
        }
    }
    {
        float2 a = s_acc[w][0][kp0][lane];
        a.x += run0.x; a.y += run0.y;
        s_acc[w][0][kp0][lane] = a;
        float2 b = s_acc[w][1][kp1][lane];
        b.x += run1.x; b.y += run1.y;
        s_acc[w][1][kp1][lane] = b;
    }
    __syncthreads();

    // merge warps + stream halves -> g_part[bc][p][z][k][16]
    for (int j = tid; j < 2 * NBINS * 16; j += 64) {
        int pp = j / (NBINS * 16);
        int r  = j % (NBINS * 16);
        int k  = r >> 4;
        int ch = r & 15;
        float2 acc = make_float2(0.f, 0.f);
#pragma unroll
        for (int w2 = 0; w2 < 2; w2++) {
            float2 a = s_acc[w2][pp][k][ch];
            float2 b = s_acc[w2][pp][k][ch + 16];
            acc.x += a.x + b.x;
            acc.y += a.y + b.y;
        }
        g_part[bc][p0 + pp][z][k][ch] = acc;
    }

    // last-block-done reduce (fused mi_reduce)
    __threadfence();
    if (tid == 0) s_old = atomicAdd(&g_cnt[bc][px], 1);
    __syncthreads();
    if (s_old != TS2 - 1) return;
    __threadfence();

    int p  = p0 + w;                    // warp w -> its p
    int cl = lane & 15;
    float2 means[NBINS];
    float2 tot = make_float2(0.f, 0.f);
#pragma unroll
    for (int k = 0; k < NBINS; k++) {
        float2 s = make_float2(0.f, 0.f);
#pragma unroll
        for (int zz = 0; zz < TS2; zz++) {
            float2 a = g_part[bc][p][zz][k][cl];
            s.x += a.x; s.y += a.y;
        }
        float cnt = __shfl_sync(0xffffffffu, s.x, 15);
        float2 m;
        m.x = __fdiv_rn(s.x, fmaxf(cnt, 1e-9f));
        m.y = __fdiv_rn(s.y, fmaxf(cnt, 1e-9f));
        means[k] = m;
        tot.x += m.x; tot.y += m.y;
    }
    float2 denom = make_float2(fmaxf(tot.x, 1e-9f), fmaxf(tot.y, 1e-9f));
    float2 acc = make_float2(0.f, 0.f);
#pragma unroll
    for (int k = 0; k < NBINS; k++) {
        float prx = __fdiv_rn(means[k].x, denom.x);
        float pry = __fdiv_rn(means[k].y, denom.y);
        acc.x += prx * logf(prx + 1e-9f);
        acc.y += pry * logf(pry + 1e-9f);
    }
    const float LOG_NB = 2.8903717578961645f;
    if (lane < 15) {
        float* o = &out[(bc * PHA_NB + p) * AMP_NB];
        o[2 * lane]     = (LOG_NB + acc.x) / LOG_NB;
        o[2 * lane + 1] = (LOG_NB + acc.y) / LOG_NB;
    }
}

// ---------------- launch -----------------------------------------------------
extern "C" void kernel_launch(void* const* d_in, const int* in_sizes, int n_in,
                              void* d_out, int out_size) {
    const float* x = (const float*)d_in[0];
    float* out = (float*)d_out;

    dft_kernel<<<NBC, 1024>>>(x);
    prefix_kernel<<<dim3(NKEEP / 128, NBC, NCH), 128>>>();
    tail_kernel<<<dim3(NKEEP / 128, NBC, 5), 128>>>();
    mi_part_kernel<<<dim3(PHA_NB / 2, NBC, TS2), 64>>>(out);
}